// round 4
// baseline (speedup 1.0000x reference)
#include <cuda_runtime.h>
#include <cuda_bf16.h>

#define HW_  4096
#define C_   256
#define B_   4

// Scratch (allocation-free rule: __device__ globals)
__device__ float g_x1[B_ * C_ * HW_];            // relu(conv(ref,w1))  [b][c][pos]
__device__ float g_v [B_ * C_ * HW_];            // relu(conv(ref,w2))  [b][c][pos]
__device__ float g_S [(size_t)B_ * HW_ * HW_];   // raw scores (symmetric per batch)
__device__ float g_mx [B_ * HW_];                // colmax  (== rowmax by symmetry)
__device__ float g_rcp[B_ * HW_];                // 1 / colsum per (b, m)

// ---------------------------------------------------------------------------
// FMA-pipe exp (x <= 0 expected). 2^f Taylor(6) after range reduction.
// ---------------------------------------------------------------------------
__device__ __forceinline__ float fast_exp(float x) {
    x = fmaxf(x, -87.0f);
    float y  = x * 1.4426950408889634f;     // log2(e)
    float fl = floorf(y);
    float f  = y - fl;                       // [0,1)
    float t  = f * 0.6931471805599453f;      // f*ln2
    float p = 1.3888889e-3f;                 // 1/720
    p = fmaf(p, t, 8.3333333e-3f);           // 1/120
    p = fmaf(p, t, 4.1666667e-2f);           // 1/24
    p = fmaf(p, t, 1.6666667e-1f);           // 1/6
    p = fmaf(p, t, 0.5f);
    p = fmaf(p, t, 1.0f);
    p = fmaf(p, t, 1.0f);
    int e = (int)fl;
    return __int_as_float((e + 127) << 23) * p;
}

// ---------------------------------------------------------------------------
// Conv 3x3 SAME + ReLU as implicit GEMM: M=256 (co), N=16384 (b,pos), K=2304
// ---------------------------------------------------------------------------
__global__ __launch_bounds__(256) void conv_relu_kernel(
    const float* __restrict__ in, const float* __restrict__ w, int which_out)
{
    __shared__ float As[8][128];   // [k][co]
    __shared__ float Bs[8][128];   // [k][n]
    float* __restrict__ out = which_out ? g_v : g_x1;

    const int t    = threadIdx.x;
    const int m0   = blockIdx.y * 128;       // co base
    const int n0   = blockIdx.x * 128;       // global spatial base (b*4096 + pos)
    const int b    = n0 >> 12;
    const int pos0 = n0 & 4095;

    const int tm = (t >> 4) * 8;
    const int tn = (t & 15) * 8;
    const int a_row  = t >> 1;
    const int a_koff = (t & 1) * 4;

    float acc[8][8] = {};

    for (int k0 = 0; k0 < 2304; k0 += 8) {
        float4 av = *(const float4*)(w + (m0 + a_row) * 2304 + k0 + a_koff);
        As[a_koff + 0][a_row] = av.x;
        As[a_koff + 1][a_row] = av.y;
        As[a_koff + 2][a_row] = av.z;
        As[a_koff + 3][a_row] = av.w;
        #pragma unroll
        for (int i = 0; i < 4; i++) {
            int idx = t + i * 256;
            int kk  = idx >> 7;
            int col = idx & 127;
            int kg  = k0 + kk;
            int ci  = kg / 9;
            int t9  = kg - ci * 9;
            int dy  = t9 / 3 - 1;
            int dx  = t9 - (t9 / 3) * 3 - 1;
            int pos = pos0 + col;
            int y   = pos >> 6, x = pos & 63;
            int yy  = y + dy,  xx = x + dx;
            float val = 0.0f;
            if ((unsigned)yy < 64u && (unsigned)xx < 64u)
                val = in[(((b << 8) + ci) << 12) + (yy << 6) + xx];
            Bs[kk][col] = val;
        }
        __syncthreads();
        #pragma unroll
        for (int k = 0; k < 8; k++) {
            float4 a0 = *(const float4*)&As[k][tm];
            float4 a1 = *(const float4*)&As[k][tm + 4];
            float4 b0 = *(const float4*)&Bs[k][tn];
            float4 b1 = *(const float4*)&Bs[k][tn + 4];
            float ar[8] = {a0.x, a0.y, a0.z, a0.w, a1.x, a1.y, a1.z, a1.w};
            float br[8] = {b0.x, b0.y, b0.z, b0.w, b1.x, b1.y, b1.z, b1.w};
            #pragma unroll
            for (int i = 0; i < 8; i++)
                #pragma unroll
                for (int j = 0; j < 8; j++)
                    acc[i][j] = fmaf(ar[i], br[j], acc[i][j]);
        }
        __syncthreads();
    }
    #pragma unroll
    for (int i = 0; i < 8; i++) {
        int m = m0 + tm + i;
        float* op = out + (((b << 8) + m) << 12) + pos0 + tn;
        #pragma unroll
        for (int j = 0; j < 8; j++)
            op[j] = fmaxf(acc[i][j], 0.0f);
    }
}

// ---------------------------------------------------------------------------
// S[b][n][m] = sum_c x1[b][c][n] * x1[b][c][m]   (M=N=4096, K=256)
// ---------------------------------------------------------------------------
__global__ __launch_bounds__(256) void scores_kernel()
{
    __shared__ float As[8][128];   // [k][n]
    __shared__ float Bs[8][128];   // [k][m]
    const int t     = threadIdx.x;
    const int b     = blockIdx.z;
    const int nbase = blockIdx.y * 128;
    const int mbase = blockIdx.x * 128;
    const float* __restrict__ Xb = g_x1 + b * C_ * HW_;

    const int tm = (t >> 4) * 8;
    const int tn = (t & 15) * 8;
    float acc[8][8] = {};

    for (int k0 = 0; k0 < 256; k0 += 8) {
        #pragma unroll
        for (int i = 0; i < 4; i++) {
            int idx = t + i * 256;
            int kk  = idx >> 7;
            int col = idx & 127;
            As[kk][col] = Xb[(k0 + kk) * HW_ + nbase + col];
            Bs[kk][col] = Xb[(k0 + kk) * HW_ + mbase + col];
        }
        __syncthreads();
        #pragma unroll
        for (int k = 0; k < 8; k++) {
            float4 a0 = *(const float4*)&As[k][tm];
            float4 a1 = *(const float4*)&As[k][tm + 4];
            float4 b0 = *(const float4*)&Bs[k][tn];
            float4 b1 = *(const float4*)&Bs[k][tn + 4];
            float ar[8] = {a0.x, a0.y, a0.z, a0.w, a1.x, a1.y, a1.z, a1.w};
            float br[8] = {b0.x, b0.y, b0.z, b0.w, b1.x, b1.y, b1.z, b1.w};
            #pragma unroll
            for (int i = 0; i < 8; i++)
                #pragma unroll
                for (int j = 0; j < 8; j++)
                    acc[i][j] = fmaf(ar[i], br[j], acc[i][j]);
        }
        __syncthreads();
    }
    float* Sp = g_S + (size_t)b * HW_ * HW_;
    #pragma unroll
    for (int i = 0; i < 8; i++) {
        float* row = Sp + (size_t)(nbase + tm + i) * HW_ + mbase + tn;
        #pragma unroll
        for (int j = 0; j < 8; j++) row[j] = acc[i][j];
    }
}

// ---------------------------------------------------------------------------
// Softmax stats via symmetry: column m stats over n == row m stats.
// One block per row; contiguous float4 reads; single pass (values kept in regs).
// ---------------------------------------------------------------------------
__global__ __launch_bounds__(256) void rowstats_kernel()
{
    __shared__ float red[256];
    const int b = blockIdx.y;
    const int m = blockIdx.x;
    const int t = threadIdx.x;
    const float* __restrict__ row = g_S + ((size_t)b * HW_ + m) * HW_;

    float4 v[4];
    #pragma unroll
    for (int i = 0; i < 4; i++)
        v[i] = *(const float4*)(row + i * 1024 + t * 4);

    float mx = -1e30f;
    #pragma unroll
    for (int i = 0; i < 4; i++) {
        mx = fmaxf(mx, fmaxf(fmaxf(v[i].x, v[i].y), fmaxf(v[i].z, v[i].w)));
    }
    red[t] = mx;
    __syncthreads();
    #pragma unroll
    for (int s = 128; s >= 32; s >>= 1) {
        if (t < s) red[t] = fmaxf(red[t], red[t + s]);
        __syncthreads();
    }
    if (t < 32) {
        float r = red[t];
        #pragma unroll
        for (int o = 16; o > 0; o >>= 1)
            r = fmaxf(r, __shfl_xor_sync(0xffffffffu, r, o));
        red[0] = r;
    }
    __syncthreads();
    mx = red[0];
    __syncthreads();

    float sum = 0.0f;
    #pragma unroll
    for (int i = 0; i < 4; i++) {
        sum += fast_exp(v[i].x - mx) + fast_exp(v[i].y - mx)
             + fast_exp(v[i].z - mx) + fast_exp(v[i].w - mx);
    }
    red[t] = sum;
    __syncthreads();
    #pragma unroll
    for (int s = 128; s >= 32; s >>= 1) {
        if (t < s) red[t] += red[t + s];
        __syncthreads();
    }
    if (t < 32) {
        float r = red[t];
        #pragma unroll
        for (int o = 16; o > 0; o >>= 1)
            r += __shfl_xor_sync(0xffffffffu, r, o);
        if (t == 0) {
            g_mx [b * HW_ + m] = mx;
            g_rcp[b * HW_ + m] = 1.0f / r;
        }
    }
}

// ---------------------------------------------------------------------------
// A = v @ exp(S - mx[m]),  out = gamma * A * rcp[m] + ref
// M=256 (c), N=4096 (m), K=4096 (n), per batch. exp fused into B-tile load.
// ---------------------------------------------------------------------------
__global__ __launch_bounds__(256) void av_kernel(
    const float* __restrict__ ref, const float* __restrict__ gamma_p,
    float* __restrict__ out)
{
    __shared__ float As[8][128];   // [k][c]
    __shared__ float Bs[8][128];   // [k][m]
    __shared__ float s_mx[128];
    const int t  = threadIdx.x;
    const int b  = blockIdx.z;
    const int c0 = blockIdx.y * 128;
    const int m0 = blockIdx.x * 128;
    const float* __restrict__ Vb = g_v + b * C_ * HW_;
    const float* __restrict__ Sb = g_S + (size_t)b * HW_ * HW_;

    if (t < 128) s_mx[t] = g_mx[b * HW_ + m0 + t];
    __syncthreads();

    const int tm = (t >> 4) * 8;
    const int tn = (t & 15) * 8;
    const int a_row  = t >> 1;
    const int a_koff = (t & 1) * 4;
    float acc[8][8] = {};

    for (int k0 = 0; k0 < HW_; k0 += 8) {
        float4 av = *(const float4*)(Vb + (c0 + a_row) * HW_ + k0 + a_koff);
        As[a_koff + 0][a_row] = av.x;
        As[a_koff + 1][a_row] = av.y;
        As[a_koff + 2][a_row] = av.z;
        As[a_koff + 3][a_row] = av.w;
        #pragma unroll
        for (int i = 0; i < 4; i++) {
            int idx = t + i * 256;
            int kk  = idx >> 7;
            int col = idx & 127;
            float s = Sb[(size_t)(k0 + kk) * HW_ + m0 + col];
            Bs[kk][col] = fast_exp(s - s_mx[col]);
        }
        __syncthreads();
        #pragma unroll
        for (int k = 0; k < 8; k++) {
            float4 a0 = *(const float4*)&As[k][tm];
            float4 a1 = *(const float4*)&As[k][tm + 4];
            float4 b0 = *(const float4*)&Bs[k][tn];
            float4 b1 = *(const float4*)&Bs[k][tn + 4];
            float ar[8] = {a0.x, a0.y, a0.z, a0.w, a1.x, a1.y, a1.z, a1.w};
            float br[8] = {b0.x, b0.y, b0.z, b0.w, b1.x, b1.y, b1.z, b1.w};
            #pragma unroll
            for (int i = 0; i < 8; i++)
                #pragma unroll
                for (int j = 0; j < 8; j++)
                    acc[i][j] = fmaf(ar[i], br[j], acc[i][j]);
        }
        __syncthreads();
    }

    const float g = *gamma_p;
    float rc[8];
    #pragma unroll
    for (int j = 0; j < 8; j++) rc[j] = g * g_rcp[b * HW_ + m0 + tn + j];

    #pragma unroll
    for (int i = 0; i < 8; i++) {
        int c = c0 + tm + i;
        size_t base = (((size_t)b * C_ + c) * HW_) + m0 + tn;
        const float* rp = ref + base;
        float* op = out + base;
        #pragma unroll
        for (int j = 0; j < 8; j++)
            op[j] = fmaf(acc[i][j], rc[j], rp[j]);
    }
}

// ---------------------------------------------------------------------------
extern "C" void kernel_launch(void* const* d_in, const int* in_sizes, int n_in,
                              void* d_out, int out_size)
{
    // metadata order: inputs, ref, w1, w2, gamma
    // 'inputs' is dead in the reference (its conv result is overwritten) -> skip it.
    const float* ref   = (const float*)d_in[1];
    const float* w1    = (const float*)d_in[2];
    const float* w2    = (const float*)d_in[3];
    const float* gamma = (const float*)d_in[4];
    float* out = (float*)d_out;

    conv_relu_kernel<<<dim3(128, 2), 256>>>(ref, w1, 0);
    conv_relu_kernel<<<dim3(128, 2), 256>>>(ref, w2, 1);
    scores_kernel<<<dim3(32, 32, 4), 256>>>();
    rowstats_kernel<<<dim3(4096, 4), 256>>>();
    av_kernel<<<dim3(32, 2, 4), 256>>>(ref, gamma, out);
}

// round 6
// speedup vs baseline: 2.5174x; 2.5174x over previous
#include <cuda_runtime.h>
#include <cuda_bf16.h>
#include <cstdint>

#define HW_  4096
#define C_   256
#define B_   4

// ---------------- scratch (__device__ globals per allocation rules) --------
__device__ __align__(1024) __nv_bfloat16 g_refTh[B_ * HW_ * C_]; // [b*4096+pos][ci]
__device__ __align__(1024) __nv_bfloat16 g_refTl[B_ * HW_ * C_];
__device__ __align__(1024) __nv_bfloat16 g_wh[2 * 9 * C_ * C_];  // [w][s][co][ci]
__device__ __align__(1024) __nv_bfloat16 g_wl[2 * 9 * C_ * C_];
__device__ __align__(1024) __nv_bfloat16 g_x1th[B_ * HW_ * C_]; // [b*4096+pos][c]
__device__ __align__(1024) __nv_bfloat16 g_x1tl[B_ * HW_ * C_];
__device__ __align__(1024) __nv_bfloat16 g_Vh[B_ * C_ * HW_];   // [b][c][pos]
__device__ __align__(1024) __nv_bfloat16 g_Vl[B_ * C_ * HW_];
__device__ float g_S[(size_t)B_ * HW_ * HW_];
__device__ float g_mx[B_ * HW_];
__device__ float g_rcp[B_ * HW_];

// ---------------- smem layout (shared by all GEMM kernels) -----------------
// mainloop: Ah@0 Al@16K Bh@32K Bl@48K (each 128 rows x 128B, SW128)
// epilogue: fp32 staging st[128][129] @0 (66048 B)
// aux:      mx @66048 (512B), rc @66560 (512B)
#define SM_AH 0
#define SM_AL 16384
#define SM_BH 32768
#define SM_BL 49152
#define SM_AUX 66048
#define SMEM_SZ 67072

__device__ __forceinline__ uint32_t smem_u32(const void* p) {
    uint32_t a;
    asm("{ .reg .u64 t; cvta.to.shared.u64 t, %1; cvt.u32.u64 %0, t; }" : "=r"(a) : "l"(p));
    return a;
}
#define SW128(o) ((o) ^ (((o) >> 3) & 0x70))

__device__ __forceinline__ void ldm4(uint32_t r[4], uint32_t addr) {
    asm volatile("ldmatrix.sync.aligned.m8n8.x4.shared.b16 {%0,%1,%2,%3}, [%4];"
        : "=r"(r[0]), "=r"(r[1]), "=r"(r[2]), "=r"(r[3]) : "r"(addr));
}
__device__ __forceinline__ void mma_bf16(float d[4], const uint32_t a[4],
                                         uint32_t b0, uint32_t b1) {
    asm volatile("mma.sync.aligned.m16n8k16.row.col.f32.bf16.bf16.f32 "
        "{%0,%1,%2,%3}, {%4,%5,%6,%7}, {%8,%9}, {%0,%1,%2,%3};"
        : "+f"(d[0]), "+f"(d[1]), "+f"(d[2]), "+f"(d[3])
        : "r"(a[0]), "r"(a[1]), "r"(a[2]), "r"(a[3]), "r"(b0), "r"(b1));
}

// 3-term split-bf16 K=64 chunk on one warp tile (32m x 64n):
// acc += Ah*Bh + Ah*Bl + Al*Bh
__device__ __forceinline__ void warp_chunk3(float acc[2][8][4],
    uint32_t sAh, uint32_t sAl, uint32_t sBh, uint32_t sBl,
    int wm, int wn, int lane)
{
    const int tile = lane >> 3, tr = lane & 7;
    #pragma unroll
    for (int kk = 0; kk < 4; kk++) {
        uint32_t ah[2][4], al[2][4];
        #pragma unroll
        for (int mf = 0; mf < 2; mf++) {
            int row = wm + mf * 16 + ((tile & 1) << 3) + tr;
            int g   = 2 * kk + (tile >> 1);
            uint32_t off = SW128((uint32_t)(row * 128 + g * 16));
            ldm4(ah[mf], sAh + off);
            ldm4(al[mf], sAl + off);
        }
        #pragma unroll
        for (int nf = 0; nf < 8; nf += 2) {
            int row = wn + nf * 8 + ((tile >> 1) << 3) + tr;
            int g   = 2 * kk + (tile & 1);
            uint32_t off = SW128((uint32_t)(row * 128 + g * 16));
            uint32_t bh[4], bl[4];
            ldm4(bh, sBh + off);
            ldm4(bl, sBl + off);
            #pragma unroll
            for (int mf = 0; mf < 2; mf++) {
                mma_bf16(acc[mf][nf],     ah[mf], bh[0], bh[1]);
                mma_bf16(acc[mf][nf],     ah[mf], bl[0], bl[1]);
                mma_bf16(acc[mf][nf],     al[mf], bh[0], bh[1]);
                mma_bf16(acc[mf][nf + 1], ah[mf], bh[2], bh[3]);
                mma_bf16(acc[mf][nf + 1], ah[mf], bl[2], bl[3]);
                mma_bf16(acc[mf][nf + 1], al[mf], bh[2], bh[3]);
            }
        }
    }
}

// accumulators -> fp32 staging st[m*129+n]
__device__ __forceinline__ void acc_to_staging(float* st, float acc[2][8][4],
                                               int wm, int wn, int lane, bool relu) {
    const int r0 = lane >> 2, c0 = (lane & 3) * 2;
    #pragma unroll
    for (int mf = 0; mf < 2; mf++)
        #pragma unroll
        for (int nf = 0; nf < 8; nf++)
            #pragma unroll
            for (int i = 0; i < 4; i++) {
                int m = wm + mf * 16 + r0 + (i >> 1) * 8;
                int n = wn + nf * 8 + c0 + (i & 1);
                float v = acc[mf][nf][i];
                st[m * 129 + n] = relu ? fmaxf(v, 0.0f) : v;
            }
}

// 128x64 bf16 K-major tile fill (swizzled), rstride in elements
__device__ __forceinline__ void fill64(char* dst, const __nv_bfloat16* src, int rstride) {
    int t = threadIdx.x;
    #pragma unroll
    for (int i = 0; i < 4; i++) {
        int idx = t + i * 256, r = idx >> 3, ch = idx & 7;
        *(uint4*)(dst + SW128((uint32_t)(r * 128 + ch * 16))) =
            *(const uint4*)(src + (size_t)r * rstride + ch * 8);
    }
}

__device__ __forceinline__ void split_store(float v, __nv_bfloat16* ph, __nv_bfloat16* pl, size_t o) {
    __nv_bfloat16 h = __float2bfloat16(v);
    ph[o] = h;
    pl[o] = __float2bfloat16(v - __bfloat162float(h));
}

__device__ __forceinline__ float fast_exp(float x) {
    x = fmaxf(x, -87.0f);
    float y  = x * 1.4426950408889634f;
    float fl = floorf(y);
    float t  = (y - fl) * 0.6931471805599453f;
    float p = 1.3888889e-3f;
    p = fmaf(p, t, 8.3333333e-3f);
    p = fmaf(p, t, 4.1666667e-2f);
    p = fmaf(p, t, 1.6666667e-1f);
    p = fmaf(p, t, 0.5f);
    p = fmaf(p, t, 1.0f);
    p = fmaf(p, t, 1.0f);
    return __int_as_float(((int)fl + 127) << 23) * p;
}

// ---------------- prep: weights -> [w][s][co][ci] hi/lo --------------------
__global__ __launch_bounds__(256) void prep_w_kernel(
    const float* __restrict__ w1, const float* __restrict__ w2)
{
    int idx = blockIdx.x * 256 + threadIdx.x;        // < 1179648
    int w = idx / 589824, r = idx - w * 589824;
    int s = r >> 16, r2 = r & 65535, co = r2 >> 8, ci = r2 & 255;
    const float* wp = w ? w2 : w1;
    split_store(wp[co * 2304 + ci * 9 + s], g_wh, g_wl, (size_t)idx);
}

// ---------------- prep: ref [b][c][pos] -> refT [b][pos][ci] hi/lo ---------
__global__ void prep_refT_kernel(const float* __restrict__ ref)
{
    __shared__ float tile[32][33];
    int b = blockIdx.z, p0 = blockIdx.x * 32, c0 = blockIdx.y * 32;
    int x = threadIdx.x, y = threadIdx.y;            // (32, 8)
    #pragma unroll
    for (int i = 0; i < 4; i++)
        tile[y + i * 8][x] = ref[((size_t)(b * 256 + c0 + y + i * 8)) * 4096 + p0 + x];
    __syncthreads();
    #pragma unroll
    for (int i = 0; i < 4; i++) {
        int p = y + i * 8;
        split_store(tile[x][p], g_refTh, g_refTl,
                    ((size_t)((b << 12) + p0 + p)) * 256 + c0 + x);
    }
}

// ---------------- conv 3x3 SAME + relu via mma.sync ------------------------
// grid (32 pos-tiles, 4 = w*2+half, B_). D[co 128][pos 128].
__global__ __launch_bounds__(256) void conv_mma_kernel()
{
    extern __shared__ char sm[];
    const uint32_t sb = smem_u32(sm);
    const int t = threadIdx.x, lane = t & 31, wid = t >> 5;
    const int wm = (wid & 3) * 32, wn = (wid >> 2) * 64;
    const int pos0 = blockIdx.x * 128;
    const int w = blockIdx.y >> 1, half = blockIdx.y & 1;
    const int b = blockIdx.z;
    float acc[2][8][4] = {};

    for (int s = 0; s < 9; s++) {
        int dy = s / 3 - 1, dx = s % 3 - 1, shift = dy * 64 + dx;
        for (int cc = 0; cc < 4; cc++) {
            int ci0 = cc * 64;
            // A = weights [co][ci chunk]
            const size_t wbase = ((size_t)((w * 9 + s) * 256 + half * 128)) * 256 + ci0;
            fill64(sm + SM_AH, g_wh + wbase, 256);
            fill64(sm + SM_AL, g_wl + wbase, 256);
            // B = activations with SAME-pad masks
            #pragma unroll
            for (int i = 0; i < 4; i++) {
                int idx = t + i * 256, r = idx >> 3, ch = idx & 7;
                int pos = pos0 + r, y = pos >> 6, x = pos & 63;
                int yy = y + dy, xx = x + dx;
                uint4 vh = {0, 0, 0, 0}, vl = {0, 0, 0, 0};
                if ((unsigned)yy < 64u && (unsigned)xx < 64u) {
                    size_t so = ((size_t)((b << 12) + pos + shift)) * 256 + ci0 + ch * 8;
                    vh = *(const uint4*)(g_refTh + so);
                    vl = *(const uint4*)(g_refTl + so);
                }
                uint32_t sw = SW128((uint32_t)(r * 128 + ch * 16));
                *(uint4*)(sm + SM_BH + sw) = vh;
                *(uint4*)(sm + SM_BL + sw) = vl;
            }
            __syncthreads();
            warp_chunk3(acc, sb + SM_AH, sb + SM_AL, sb + SM_BH, sb + SM_BL, wm, wn, lane);
            __syncthreads();
        }
    }
    // epilogue: relu + split, write x1t (w=0) or V (w=1)
    float* st = (float*)sm;
    acc_to_staging(st, acc, wm, wn, lane, true);
    __syncthreads();
    if (w == 0) {
        for (int i = t; i < 16384; i += 256) {
            int p = i >> 7, c = i & 127;      // coalesced over c
            split_store(st[c * 129 + p], g_x1th, g_x1tl,
                        ((size_t)((b << 12) + pos0 + p)) * 256 + half * 128 + c);
        }
    } else {
        for (int i = t; i < 16384; i += 256) {
            int c = i >> 7, p = i & 127;      // coalesced over p
            split_store(st[c * 129 + p], g_Vh, g_Vl,
                        ((size_t)((b << 8) + half * 128 + c)) * 4096 + pos0 + p);
        }
    }
}

// ---------------- scores = x1t . x1t^T (symmetric, triangular grid) --------
__global__ __launch_bounds__(256) void scores_mma_kernel()
{
    extern __shared__ char sm[];
    const uint32_t sb = smem_u32(sm);
    const int t = threadIdx.x, lane = t & 31, wid = t >> 5;
    const int wm = (wid & 3) * 32, wn = (wid >> 2) * 64;
    const int b = blockIdx.y;
    int i = 0, pp = blockIdx.x;
    while (pp >= 32 - i) { pp -= 32 - i; i++; }
    const int n0 = i * 128, m0 = (i + pp) * 128;
    float acc[2][8][4] = {};

    for (int kc = 0; kc < 4; kc++) {
        int k0 = kc * 64;
        fill64(sm + SM_AH, g_x1th + ((size_t)((b << 12) + n0)) * 256 + k0, 256);
        fill64(sm + SM_AL, g_x1tl + ((size_t)((b << 12) + n0)) * 256 + k0, 256);
        fill64(sm + SM_BH, g_x1th + ((size_t)((b << 12) + m0)) * 256 + k0, 256);
        fill64(sm + SM_BL, g_x1tl + ((size_t)((b << 12) + m0)) * 256 + k0, 256);
        __syncthreads();
        warp_chunk3(acc, sb + SM_AH, sb + SM_AL, sb + SM_BH, sb + SM_BL, wm, wn, lane);
        __syncthreads();
    }
    float* st = (float*)sm;
    acc_to_staging(st, acc, wm, wn, lane, false);
    __syncthreads();
    float* Sb = g_S + (size_t)b * HW_ * HW_;
    for (int ii = t; ii < 16384; ii += 256) {
        int r = ii >> 7, c = ii & 127;
        Sb[(size_t)(n0 + r) * 4096 + m0 + c] = st[r * 129 + c];
    }
    if (n0 != m0) {
        for (int ii = t; ii < 16384; ii += 256) {
            int r = ii >> 7, c = ii & 127;
            Sb[(size_t)(m0 + r) * 4096 + n0 + c] = st[c * 129 + r];
        }
    }
}

// ---------------- row stats (== column stats by symmetry) ------------------
__global__ __launch_bounds__(256) void rowstats_kernel()
{
    __shared__ float red[256];
    const int b = blockIdx.y, m = blockIdx.x, t = threadIdx.x;
    const float* __restrict__ row = g_S + ((size_t)b * HW_ + m) * HW_;
    float4 v[4];
    #pragma unroll
    for (int i = 0; i < 4; i++) v[i] = *(const float4*)(row + i * 1024 + t * 4);
    float mx = -1e30f;
    #pragma unroll
    for (int i = 0; i < 4; i++)
        mx = fmaxf(mx, fmaxf(fmaxf(v[i].x, v[i].y), fmaxf(v[i].z, v[i].w)));
    red[t] = mx;
    __syncthreads();
    #pragma unroll
    for (int s = 128; s >= 32; s >>= 1) {
        if (t < s) red[t] = fmaxf(red[t], red[t + s]);
        __syncthreads();
    }
    if (t < 32) {
        float r = red[t];
        #pragma unroll
        for (int o = 16; o > 0; o >>= 1) r = fmaxf(r, __shfl_xor_sync(~0u, r, o));
        red[0] = r;
    }
    __syncthreads();
    mx = red[0];
    __syncthreads();
    float sum = 0.0f;
    #pragma unroll
    for (int i = 0; i < 4; i++)
        sum += fast_exp(v[i].x - mx) + fast_exp(v[i].y - mx)
             + fast_exp(v[i].z - mx) + fast_exp(v[i].w - mx);
    red[t] = sum;
    __syncthreads();
    #pragma unroll
    for (int s = 128; s >= 32; s >>= 1) {
        if (t < s) red[t] += red[t + s];
        __syncthreads();
    }
    if (t < 32) {
        float r = red[t];
        #pragma unroll
        for (int o = 16; o > 0; o >>= 1) r += __shfl_xor_sync(~0u, r, o);
        if (t == 0) { g_mx[b * HW_ + m] = mx; g_rcp[b * HW_ + m] = 1.0f / r; }
    }
}

// ---------------- AV: out = gamma * rcp[m] * (V . E) + ref -----------------
// grid (32 m-tiles, 2 c-halves, B_). k = n (4096), E on the fly from S rows.
__global__ __launch_bounds__(256) void av_mma_kernel(
    const float* __restrict__ ref, const float* __restrict__ gamma_p,
    float* __restrict__ out)
{
    extern __shared__ char sm[];
    const uint32_t sb = smem_u32(sm);
    const int t = threadIdx.x, lane = t & 31, wid = t >> 5;
    const int wm = (wid & 3) * 32, wn = (wid >> 2) * 64;
    const int m0 = blockIdx.x * 128, chalf = blockIdx.y, b = blockIdx.z;
    float* s_mx = (float*)(sm + SM_AUX);
    if (t < 128) s_mx[t] = g_mx[(b << 12) + m0 + t];
    __syncthreads();
    const float* Sb = g_S + (size_t)b * HW_ * HW_;
    float acc[2][8][4] = {};

    for (int kc = 0; kc < 64; kc++) {
        int k0 = kc * 64;
        const size_t vbase = ((size_t)((b << 8) + chalf * 128)) * 4096 + k0;
        fill64(sm + SM_AH, g_Vh + vbase, 4096);
        fill64(sm + SM_AL, g_Vl + vbase, 4096);
        // B rows = output col m, k-cols = n: E[n][m] = exp(S[m][n] - mx[m])
        #pragma unroll
        for (int i = 0; i < 4; i++) {
            int idx = t + i * 256, r = idx >> 3, ch = idx & 7;
            const float* sp = Sb + (size_t)(m0 + r) * 4096 + k0 + ch * 8;
            float mxr = s_mx[r];
            __nv_bfloat16 hh[8], ll[8];
            #pragma unroll
            for (int j = 0; j < 8; j++) {
                float e = fast_exp(sp[j] - mxr);
                __nv_bfloat16 h = __float2bfloat16(e);
                hh[j] = h;
                ll[j] = __float2bfloat16(e - __bfloat162float(h));
            }
            uint32_t sw = SW128((uint32_t)(r * 128 + ch * 16));
            *(uint4*)(sm + SM_BH + sw) = *(uint4*)hh;
            *(uint4*)(sm + SM_BL + sw) = *(uint4*)ll;
        }
        __syncthreads();
        warp_chunk3(acc, sb + SM_AH, sb + SM_AL, sb + SM_BH, sb + SM_BL, wm, wn, lane);
        __syncthreads();
    }
    // epilogue
    float* st = (float*)sm;
    acc_to_staging(st, acc, wm, wn, lane, false);
    float* s_rc = (float*)(sm + SM_AUX + 512);
    if (t < 128) s_rc[t] = (*gamma_p) * g_rcp[(b << 12) + m0 + t];
    __syncthreads();
    for (int ii = t; ii < 16384; ii += 256) {
        int cl = ii >> 7, n = ii & 127;       // coalesced over n
        size_t o = ((size_t)((b << 8) + chalf * 128 + cl)) * 4096 + m0 + n;
        out[o] = fmaf(st[cl * 129 + n], s_rc[n], ref[o]);
    }
}

// ---------------------------------------------------------------------------
extern "C" void kernel_launch(void* const* d_in, const int* in_sizes, int n_in,
                              void* d_out, int out_size)
{
    const float* ref   = (const float*)d_in[1];   // d_in[0] 'inputs' is dead in reference
    const float* w1    = (const float*)d_in[2];
    const float* w2    = (const float*)d_in[3];
    const float* gamma = (const float*)d_in[4];
    float* out = (float*)d_out;

    cudaFuncSetAttribute(conv_mma_kernel,   cudaFuncAttributeMaxDynamicSharedMemorySize, SMEM_SZ);
    cudaFuncSetAttribute(scores_mma_kernel, cudaFuncAttributeMaxDynamicSharedMemorySize, SMEM_SZ);
    cudaFuncSetAttribute(av_mma_kernel,     cudaFuncAttributeMaxDynamicSharedMemorySize, SMEM_SZ);

    prep_w_kernel<<<4608, 256>>>(w1, w2);
    prep_refT_kernel<<<dim3(128, 8, B_), dim3(32, 8)>>>(ref);
    conv_mma_kernel<<<dim3(32, 4, B_), 256, SMEM_SZ>>>();
    scores_mma_kernel<<<dim3(528, B_), 256, SMEM_SZ>>>();
    rowstats_kernel<<<dim3(4096, B_), 256>>>();
    av_mma_kernel<<<dim3(32, 2, B_), 256, SMEM_SZ>>>(ref, gamma, out);
}

// round 7
// speedup vs baseline: 3.7705x; 1.4978x over previous
#include <cuda_runtime.h>
#include <cuda_bf16.h>
#include <cstdint>

#define HW_  4096
#define C_   256
#define B_   4

// ---------------- scratch (__device__ globals per allocation rules) --------
__device__ __align__(1024) __nv_bfloat16 g_refTh[B_ * HW_ * C_]; // [b*4096+pos][ci]
__device__ __align__(1024) __nv_bfloat16 g_refTl[B_ * HW_ * C_];
__device__ __align__(1024) __nv_bfloat16 g_wh[2 * 9 * C_ * C_];  // [w][s][co][ci]
__device__ __align__(1024) __nv_bfloat16 g_wl[2 * 9 * C_ * C_];
__device__ __align__(1024) __nv_bfloat16 g_x1th[B_ * HW_ * C_]; // [b*4096+pos][c]
__device__ __align__(1024) __nv_bfloat16 g_x1tl[B_ * HW_ * C_];
__device__ __align__(1024) __nv_bfloat16 g_Vh[B_ * C_ * HW_];   // [b][c][pos]
__device__ __align__(1024) __nv_bfloat16 g_Vl[B_ * C_ * HW_];
__device__ __align__(1024) __nv_bfloat16 g_Eh[(size_t)B_ * HW_ * HW_]; // exp(S-mx) hi
__device__ __align__(1024) __nv_bfloat16 g_El[(size_t)B_ * HW_ * HW_]; // exp(S-mx) lo
__device__ float g_S[(size_t)B_ * HW_ * HW_];
__device__ float g_rcp[B_ * HW_];

// ---------------- smem layout: 2 pipeline stages + aux ---------------------
// stage s at s*65536: Ah +0, Al +16K, Bh +32K, Bl +48K (128 rows x 128B, SW128)
// epilogue fp32 staging st[128][129] aliases stage 0; aux @131072
#define SM_AH 0
#define SM_AL 16384
#define SM_BH 32768
#define SM_BL 49152
#define STG   65536
#define SM_AUX 131072
#define SMEM_SZ 132096

__device__ __forceinline__ uint32_t smem_u32(const void* p) {
    uint32_t a;
    asm("{ .reg .u64 t; cvta.to.shared.u64 t, %1; cvt.u32.u64 %0, t; }" : "=r"(a) : "l"(p));
    return a;
}
#define SW128(o) ((o) ^ (((o) >> 3) & 0x70))

__device__ __forceinline__ void cpa16(uint32_t dst, const void* src) {
    asm volatile("cp.async.cg.shared.global [%0], [%1], 16;" :: "r"(dst), "l"(src));
}
__device__ __forceinline__ void cpa16z(uint32_t dst, const void* src, bool v) {
    int sz = v ? 16 : 0;
    asm volatile("cp.async.cg.shared.global [%0], [%1], 16, %2;" :: "r"(dst), "l"(src), "r"(sz));
}
#define CP_COMMIT() asm volatile("cp.async.commit_group;" ::: "memory")
#define CP_WAIT0()  asm volatile("cp.async.wait_group 0;" ::: "memory")

__device__ __forceinline__ void ldm4(uint32_t r[4], uint32_t addr) {
    asm volatile("ldmatrix.sync.aligned.m8n8.x4.shared.b16 {%0,%1,%2,%3}, [%4];"
        : "=r"(r[0]), "=r"(r[1]), "=r"(r[2]), "=r"(r[3]) : "r"(addr));
}
__device__ __forceinline__ void mma_bf16(float d[4], const uint32_t a[4],
                                         uint32_t b0, uint32_t b1) {
    asm volatile("mma.sync.aligned.m16n8k16.row.col.f32.bf16.bf16.f32 "
        "{%0,%1,%2,%3}, {%4,%5,%6,%7}, {%8,%9}, {%0,%1,%2,%3};"
        : "+f"(d[0]), "+f"(d[1]), "+f"(d[2]), "+f"(d[3])
        : "r"(a[0]), "r"(a[1]), "r"(a[2]), "r"(a[3]), "r"(b0), "r"(b1));
}

// 3-term split-bf16 K=64 chunk on one warp tile (32m x 64n):
// acc += Ah*Bh + Ah*Bl + Al*Bh
__device__ __forceinline__ void warp_chunk3(float acc[2][8][4],
    uint32_t sAh, uint32_t sAl, uint32_t sBh, uint32_t sBl,
    int wm, int wn, int lane)
{
    const int tile = lane >> 3, tr = lane & 7;
    #pragma unroll
    for (int kk = 0; kk < 4; kk++) {
        uint32_t ah[2][4], al[2][4];
        #pragma unroll
        for (int mf = 0; mf < 2; mf++) {
            int row = wm + mf * 16 + ((tile & 1) << 3) + tr;
            int g   = 2 * kk + (tile >> 1);
            uint32_t off = SW128((uint32_t)(row * 128 + g * 16));
            ldm4(ah[mf], sAh + off);
            ldm4(al[mf], sAl + off);
        }
        #pragma unroll
        for (int nf = 0; nf < 8; nf += 2) {
            int row = wn + nf * 8 + ((tile >> 1) << 3) + tr;
            int g   = 2 * kk + (tile & 1);
            uint32_t off = SW128((uint32_t)(row * 128 + g * 16));
            uint32_t bh[4], bl[4];
            ldm4(bh, sBh + off);
            ldm4(bl, sBl + off);
            #pragma unroll
            for (int mf = 0; mf < 2; mf++) {
                mma_bf16(acc[mf][nf],     ah[mf], bh[0], bh[1]);
                mma_bf16(acc[mf][nf],     ah[mf], bl[0], bl[1]);
                mma_bf16(acc[mf][nf],     al[mf], bh[0], bh[1]);
                mma_bf16(acc[mf][nf + 1], ah[mf], bh[2], bh[3]);
                mma_bf16(acc[mf][nf + 1], ah[mf], bl[2], bl[3]);
                mma_bf16(acc[mf][nf + 1], al[mf], bh[2], bh[3]);
            }
        }
    }
}

// accumulators -> fp32 staging st[m*129+n]
__device__ __forceinline__ void acc_to_staging(float* st, float acc[2][8][4],
                                               int wm, int wn, int lane, bool relu) {
    const int r0 = lane >> 2, c0 = (lane & 3) * 2;
    #pragma unroll
    for (int mf = 0; mf < 2; mf++)
        #pragma unroll
        for (int nf = 0; nf < 8; nf++)
            #pragma unroll
            for (int i = 0; i < 4; i++) {
                int m = wm + mf * 16 + r0 + (i >> 1) * 8;
                int n = wn + nf * 8 + c0 + (i & 1);
                float v = acc[mf][nf][i];
                st[m * 129 + n] = relu ? fmaxf(v, 0.0f) : v;
            }
}

// async 128x64 bf16 K-major tile fill (swizzled), rstride in elements
__device__ __forceinline__ void fill64_async(uint32_t dst, const __nv_bfloat16* src, int rstride) {
    int t = threadIdx.x;
    #pragma unroll
    for (int i = 0; i < 4; i++) {
        int idx = t + i * 256, r = idx >> 3, ch = idx & 7;
        cpa16(dst + SW128((uint32_t)(r * 128 + ch * 16)),
              src + (size_t)r * rstride + ch * 8);
    }
}

__device__ __forceinline__ void split_store(float v, __nv_bfloat16* ph, __nv_bfloat16* pl, size_t o) {
    __nv_bfloat16 h = __float2bfloat16(v);
    ph[o] = h;
    pl[o] = __float2bfloat16(v - __bfloat162float(h));
}

__device__ __forceinline__ float fast_exp(float x) {
    x = fmaxf(x, -87.0f);
    float y  = x * 1.4426950408889634f;
    float fl = floorf(y);
    float t  = (y - fl) * 0.6931471805599453f;
    float p = 1.3888889e-3f;
    p = fmaf(p, t, 8.3333333e-3f);
    p = fmaf(p, t, 4.1666667e-2f);
    p = fmaf(p, t, 1.6666667e-1f);
    p = fmaf(p, t, 0.5f);
    p = fmaf(p, t, 1.0f);
    p = fmaf(p, t, 1.0f);
    return __int_as_float(((int)fl + 127) << 23) * p;
}

// ---------------- prep: weights -> [w][s][co][ci] hi/lo --------------------
__global__ __launch_bounds__(256) void prep_w_kernel(
    const float* __restrict__ w1, const float* __restrict__ w2)
{
    int idx = blockIdx.x * 256 + threadIdx.x;        // < 1179648
    int w = idx / 589824, r = idx - w * 589824;
    int s = r >> 16, r2 = r & 65535, co = r2 >> 8, ci = r2 & 255;
    const float* wp = w ? w2 : w1;
    split_store(wp[co * 2304 + ci * 9 + s], g_wh, g_wl, (size_t)idx);
}

// ---------------- prep: ref [b][c][pos] -> refT [b][pos][ci] hi/lo ---------
__global__ void prep_refT_kernel(const float* __restrict__ ref)
{
    __shared__ float tile[32][33];
    int b = blockIdx.z, p0 = blockIdx.x * 32, c0 = blockIdx.y * 32;
    int x = threadIdx.x, y = threadIdx.y;            // (32, 8)
    #pragma unroll
    for (int i = 0; i < 4; i++)
        tile[y + i * 8][x] = ref[((size_t)(b * 256 + c0 + y + i * 8)) * 4096 + p0 + x];
    __syncthreads();
    #pragma unroll
    for (int i = 0; i < 4; i++) {
        int p = y + i * 8;
        split_store(tile[x][p], g_refTh, g_refTl,
                    ((size_t)((b << 12) + p0 + p)) * 256 + c0 + x);
    }
}

// ---------------- conv 3x3 SAME + relu, pipelined mma.sync -----------------
// grid (32 pos-tiles, 4 = w*2+half, B_). D[co 128][pos 128]. 36 K-chunks.
__global__ __launch_bounds__(256) void conv_mma_kernel()
{
    extern __shared__ char sm[];
    const uint32_t sb = smem_u32(sm);
    const int t = threadIdx.x, lane = t & 31, wid = t >> 5;
    const int wm = (wid & 3) * 32, wn = (wid >> 2) * 64;
    const int pos0 = blockIdx.x * 128;
    const int w = blockIdx.y >> 1, half = blockIdx.y & 1;
    const int b = blockIdx.z;
    float acc[2][8][4] = {};

    auto do_fill = [&](int kc, int stg) {
        int s = kc >> 2, cc = kc & 3, ci0 = cc * 64;
        int dy = s / 3 - 1, dx = s % 3 - 1, shift = dy * 64 + dx;
        uint32_t base = sb + stg * STG;
        const size_t wbase = ((size_t)((w * 9 + s) * 256 + half * 128)) * 256 + ci0;
        #pragma unroll
        for (int i = 0; i < 4; i++) {
            int idx = t + i * 256, r = idx >> 3, ch = idx & 7;
            uint32_t sw = SW128((uint32_t)(r * 128 + ch * 16));
            cpa16(base + SM_AH + sw, g_wh + wbase + (size_t)r * 256 + ch * 8);
            cpa16(base + SM_AL + sw, g_wl + wbase + (size_t)r * 256 + ch * 8);
        }
        #pragma unroll
        for (int i = 0; i < 4; i++) {
            int idx = t + i * 256, r = idx >> 3, ch = idx & 7;
            int pos = pos0 + r, y = pos >> 6, x = pos & 63;
            int yy = y + dy, xx = x + dx;
            bool valid = ((unsigned)yy < 64u) && ((unsigned)xx < 64u);
            long long so = valid ?
                ((long long)((b << 12) + pos + shift)) * 256 + ci0 + ch * 8 : 0;
            uint32_t sw = SW128((uint32_t)(r * 128 + ch * 16));
            cpa16z(base + SM_BH + sw, g_refTh + so, valid);
            cpa16z(base + SM_BL + sw, g_refTl + so, valid);
        }
    };

    do_fill(0, 0);
    CP_COMMIT();
    for (int kc = 0; kc < 36; kc++) {
        int cur = kc & 1;
        CP_WAIT0();
        __syncthreads();
        if (kc + 1 < 36) { do_fill(kc + 1, cur ^ 1); CP_COMMIT(); }
        uint32_t base = sb + cur * STG;
        warp_chunk3(acc, base + SM_AH, base + SM_AL, base + SM_BH, base + SM_BL, wm, wn, lane);
    }
    __syncthreads();

    // epilogue: relu + split, write x1t (w=0) or V (w=1)
    float* st = (float*)sm;
    acc_to_staging(st, acc, wm, wn, lane, true);
    __syncthreads();
    if (w == 0) {
        for (int i = t; i < 16384; i += 256) {
            int p = i >> 7, c = i & 127;      // coalesced over c
            split_store(st[c * 129 + p], g_x1th, g_x1tl,
                        ((size_t)((b << 12) + pos0 + p)) * 256 + half * 128 + c);
        }
    } else {
        for (int i = t; i < 16384; i += 256) {
            int c = i >> 7, p = i & 127;      // coalesced over p
            split_store(st[c * 129 + p], g_Vh, g_Vl,
                        ((size_t)((b << 8) + half * 128 + c)) * 4096 + pos0 + p);
        }
    }
}

// ---------------- scores = x1t . x1t^T (symmetric, triangular grid) --------
__global__ __launch_bounds__(256) void scores_mma_kernel()
{
    extern __shared__ char sm[];
    const uint32_t sb = smem_u32(sm);
    const int t = threadIdx.x, lane = t & 31, wid = t >> 5;
    const int wm = (wid & 3) * 32, wn = (wid >> 2) * 64;
    const int b = blockIdx.y;
    int i = 0, pp = blockIdx.x;
    while (pp >= 32 - i) { pp -= 32 - i; i++; }
    const int n0 = i * 128, m0 = (i + pp) * 128;
    float acc[2][8][4] = {};

    auto do_fill = [&](int kc, int stg) {
        int k0 = kc * 64;
        uint32_t base = sb + stg * STG;
        fill64_async(base + SM_AH, g_x1th + ((size_t)((b << 12) + n0)) * 256 + k0, 256);
        fill64_async(base + SM_AL, g_x1tl + ((size_t)((b << 12) + n0)) * 256 + k0, 256);
        fill64_async(base + SM_BH, g_x1th + ((size_t)((b << 12) + m0)) * 256 + k0, 256);
        fill64_async(base + SM_BL, g_x1tl + ((size_t)((b << 12) + m0)) * 256 + k0, 256);
    };

    do_fill(0, 0);
    CP_COMMIT();
    for (int kc = 0; kc < 4; kc++) {
        int cur = kc & 1;
        CP_WAIT0();
        __syncthreads();
        if (kc + 1 < 4) { do_fill(kc + 1, cur ^ 1); CP_COMMIT(); }
        uint32_t base = sb + cur * STG;
        warp_chunk3(acc, base + SM_AH, base + SM_AL, base + SM_BH, base + SM_BL, wm, wn, lane);
    }
    __syncthreads();

    float* st = (float*)sm;
    acc_to_staging(st, acc, wm, wn, lane, false);
    __syncthreads();
    float* Sb = g_S + (size_t)b * HW_ * HW_;
    for (int ii = t; ii < 16384; ii += 256) {
        int r = ii >> 7, c = ii & 127;
        Sb[(size_t)(n0 + r) * 4096 + m0 + c] = st[r * 129 + c];
    }
    if (n0 != m0) {
        for (int ii = t; ii < 16384; ii += 256) {
            int r = ii >> 7, c = ii & 127;
            Sb[(size_t)(m0 + r) * 4096 + n0 + c] = st[c * 129 + r];
        }
    }
}

// ---------------- row stats + E materialization (bf16 hi/lo) ---------------
// By symmetry row stats == column stats. E[m][n] = exp(S[m][n] - mx[m]).
__global__ __launch_bounds__(256) void rowstats_kernel()
{
    __shared__ float red[256];
    const int b = blockIdx.y, m = blockIdx.x, t = threadIdx.x;
    const float* __restrict__ row = g_S + ((size_t)b * HW_ + m) * HW_;
    float4 v[4];
    #pragma unroll
    for (int i = 0; i < 4; i++) v[i] = *(const float4*)(row + i * 1024 + t * 4);
    float mx = -1e30f;
    #pragma unroll
    for (int i = 0; i < 4; i++)
        mx = fmaxf(mx, fmaxf(fmaxf(v[i].x, v[i].y), fmaxf(v[i].z, v[i].w)));
    red[t] = mx;
    __syncthreads();
    #pragma unroll
    for (int s = 128; s >= 32; s >>= 1) {
        if (t < s) red[t] = fmaxf(red[t], red[t + s]);
        __syncthreads();
    }
    if (t < 32) {
        float r = red[t];
        #pragma unroll
        for (int o = 16; o > 0; o >>= 1) r = fmaxf(r, __shfl_xor_sync(~0u, r, o));
        red[0] = r;
    }
    __syncthreads();
    mx = red[0];
    __syncthreads();
    float sum = 0.0f;
    #pragma unroll
    for (int i = 0; i < 4; i++) {
        float vv[4] = {v[i].x, v[i].y, v[i].z, v[i].w};
        __nv_bfloat16 hh[4], ll[4];
        #pragma unroll
        for (int j = 0; j < 4; j++) {
            float e = fast_exp(vv[j] - mx);
            sum += e;
            __nv_bfloat16 h = __float2bfloat16(e);
            hh[j] = h;
            ll[j] = __float2bfloat16(e - __bfloat162float(h));
        }
        size_t eo = ((size_t)((b << 12) + m)) * 4096 + i * 1024 + t * 4;
        *(uint2*)(g_Eh + eo) = *(uint2*)hh;
        *(uint2*)(g_El + eo) = *(uint2*)ll;
    }
    red[t] = sum;
    __syncthreads();
    #pragma unroll
    for (int s = 128; s >= 32; s >>= 1) {
        if (t < s) red[t] += red[t + s];
        __syncthreads();
    }
    if (t < 32) {
        float r = red[t];
        #pragma unroll
        for (int o = 16; o > 0; o >>= 1) r += __shfl_xor_sync(~0u, r, o);
        if (t == 0) g_rcp[b * HW_ + m] = 1.0f / r;
    }
}

// ---------------- AV: out = gamma * rcp[m] * (V . E^T) + ref ---------------
// grid (32 m-tiles, 2 c-halves, B_). Pure pipelined GEMM, K = n (4096).
__global__ __launch_bounds__(256) void av_mma_kernel(
    const float* __restrict__ ref, const float* __restrict__ gamma_p,
    float* __restrict__ out)
{
    extern __shared__ char sm[];
    const uint32_t sb = smem_u32(sm);
    const int t = threadIdx.x, lane = t & 31, wid = t >> 5;
    const int wm = (wid & 3) * 32, wn = (wid >> 2) * 64;
    const int m0 = blockIdx.x * 128, chalf = blockIdx.y, b = blockIdx.z;
    float acc[2][8][4] = {};

    auto do_fill = [&](int kc, int stg) {
        int k0 = kc * 64;
        uint32_t base = sb + stg * STG;
        const size_t vbase = ((size_t)((b << 8) + chalf * 128)) * 4096 + k0;
        const size_t ebase = ((size_t)((b << 12) + m0)) * 4096 + k0;
        fill64_async(base + SM_AH, g_Vh + vbase, 4096);
        fill64_async(base + SM_AL, g_Vl + vbase, 4096);
        fill64_async(base + SM_BH, g_Eh + ebase, 4096);
        fill64_async(base + SM_BL, g_El + ebase, 4096);
    };

    do_fill(0, 0);
    CP_COMMIT();
    for (int kc = 0; kc < 64; kc++) {
        int cur = kc & 1;
        CP_WAIT0();
        __syncthreads();
        if (kc + 1 < 64) { do_fill(kc + 1, cur ^ 1); CP_COMMIT(); }
        uint32_t base = sb + cur * STG;
        warp_chunk3(acc, base + SM_AH, base + SM_AL, base + SM_BH, base + SM_BL, wm, wn, lane);
    }
    __syncthreads();

    // epilogue
    float* st = (float*)sm;
    acc_to_staging(st, acc, wm, wn, lane, false);
    float* s_rc = (float*)(sm + SM_AUX);
    if (t < 128) s_rc[t] = (*gamma_p) * g_rcp[(b << 12) + m0 + t];
    __syncthreads();
    for (int ii = t; ii < 16384; ii += 256) {
        int cl = ii >> 7, n = ii & 127;       // coalesced over n
        size_t o = ((size_t)((b << 8) + chalf * 128 + cl)) * 4096 + m0 + n;
        out[o] = fmaf(st[cl * 129 + n], s_rc[n], ref[o]);
    }
}

// ---------------------------------------------------------------------------
extern "C" void kernel_launch(void* const* d_in, const int* in_sizes, int n_in,
                              void* d_out, int out_size)
{
    const float* ref   = (const float*)d_in[1];   // d_in[0] 'inputs' is dead in reference
    const float* w1    = (const float*)d_in[2];
    const float* w2    = (const float*)d_in[3];
    const float* gamma = (const float*)d_in[4];
    float* out = (float*)d_out;

    cudaFuncSetAttribute(conv_mma_kernel,   cudaFuncAttributeMaxDynamicSharedMemorySize, SMEM_SZ);
    cudaFuncSetAttribute(scores_mma_kernel, cudaFuncAttributeMaxDynamicSharedMemorySize, SMEM_SZ);
    cudaFuncSetAttribute(av_mma_kernel,     cudaFuncAttributeMaxDynamicSharedMemorySize, SMEM_SZ);

    prep_w_kernel<<<4608, 256>>>(w1, w2);
    prep_refT_kernel<<<dim3(128, 8, B_), dim3(32, 8)>>>(ref);
    conv_mma_kernel<<<dim3(32, 4, B_), 256, SMEM_SZ>>>();
    scores_mma_kernel<<<dim3(528, B_), 256, SMEM_SZ>>>();
    rowstats_kernel<<<dim3(4096, B_), 256>>>();
    av_mma_kernel<<<dim3(32, 2, B_), 256, SMEM_SZ>>>(ref, gamma, out);
}